// round 7
// baseline (speedup 1.0000x reference)
#include <cuda_runtime.h>
#include <cuda_bf16.h>
#include <mma.h>
#include <math.h>
#include <float.h>

using namespace nvcuda;

// Problem constants
#define BB 64
#define HH 1024
#define VV 32000
#define TT 20
#define KK 1024
#define GRU_KC 4
#define H0_KC 8
#define NBLK (VV / 64)       // 500 exact logits blocks
#define NSCR (VV / 128)      // 250 screening blocks
#define MARGIN 0.1f
// probe spin lengths (cycles @ ~2GHz): 1e6 ~ 0.5ms, 3e6 ~ 1.5ms
#define SPIN_BAD   1000000ll
#define SPIN_ZERO  3000000ll

// ---------------------------------------------------------------------------
// Device scratch
// ---------------------------------------------------------------------------
__device__ float g_h[2][BB * HH];
__device__ __nv_bfloat16 g_hb[BB * HH];
__device__ __nv_bfloat16 g_Wb[(size_t)VV * HH];
__device__ float g_part[GRU_KC][BB * 6 * HH];
__device__ float g_h0part[H0_KC][BB * HH];
__device__ float g_slog[BB][VV];         // screened logits (raw, no bias)
__device__ float g_pval[BB * NBLK];
__device__ int   g_pidx[BB * NBLK];
__device__ int   g_tok[BB];
__device__ int   g_probe_sink;           // keeps probe work observable

__global__ void init_tok_kernel() {
    if (threadIdx.x < BB) g_tok[threadIdx.x] = 0;  // SOS = 0
}

// ---------------------------------------------------------------------------
// W_out fp32 -> bf16 (preamble)
// ---------------------------------------------------------------------------
__global__ void wconv_kernel(const float* __restrict__ W,
                             __nv_bfloat16* __restrict__ Wb)
{
    size_t i = ((size_t)blockIdx.x * blockDim.x + threadIdx.x) * 4;
    if (i + 3 < (size_t)VV * HH) {
        float4 v = *(const float4*)(W + i);
        Wb[i + 0] = __float2bfloat16(v.x);
        Wb[i + 1] = __float2bfloat16(v.y);
        Wb[i + 2] = __float2bfloat16(v.z);
        Wb[i + 3] = __float2bfloat16(v.w);
    }
}

// ---------------------------------------------------------------------------
// Double-buffered 64x64 fp32 SGEMM core (round-2, proven)
// ---------------------------------------------------------------------------
#define GEMM_CORE(arow, wrow, kbase, klen)                                     \
    float acc[4][4] = {};                                                      \
    {                                                                          \
        float4 av = *(const float4*)((arow) + (kbase) + lk);                   \
        float4 wv = *(const float4*)((wrow) + (kbase) + lk);                   \
        As[0][lk + 0][lm] = av.x; As[0][lk + 1][lm] = av.y;                    \
        As[0][lk + 2][lm] = av.z; As[0][lk + 3][lm] = av.w;                    \
        Bs[0][lk + 0][lm] = wv.x; Bs[0][lk + 1][lm] = wv.y;                    \
        Bs[0][lk + 2][lm] = wv.z; Bs[0][lk + 3][lm] = wv.w;                    \
    }                                                                          \
    __syncthreads();                                                           \
    int buf = 0;                                                               \
    for (int k0 = 16; k0 <= (klen); k0 += 16) {                                \
        float4 av2, wv2;                                                       \
        const bool more = (k0 < (klen));                                       \
        if (more) {                                                            \
            av2 = *(const float4*)((arow) + (kbase) + k0 + lk);                \
            wv2 = *(const float4*)((wrow) + (kbase) + k0 + lk);                \
        }                                                                      \
        _Pragma("unroll")                                                      \
        for (int kk = 0; kk < 16; kk++) {                                      \
            float4 a = *(const float4*)&As[buf][kk][ty * 4];                   \
            float4 b = *(const float4*)&Bs[buf][kk][tx * 4];                   \
            float af[4] = {a.x, a.y, a.z, a.w};                                \
            float bf[4] = {b.x, b.y, b.z, b.w};                                \
            _Pragma("unroll")                                                  \
            for (int i = 0; i < 4; i++)                                        \
                _Pragma("unroll")                                              \
                for (int j = 0; j < 4; j++)                                    \
                    acc[i][j] = fmaf(af[i], bf[j], acc[i][j]);                 \
        }                                                                      \
        if (more) {                                                            \
            As[buf ^ 1][lk + 0][lm] = av2.x; As[buf ^ 1][lk + 1][lm] = av2.y;  \
            As[buf ^ 1][lk + 2][lm] = av2.z; As[buf ^ 1][lk + 3][lm] = av2.w;  \
            Bs[buf ^ 1][lk + 0][lm] = wv2.x; Bs[buf ^ 1][lk + 1][lm] = wv2.y;  \
            Bs[buf ^ 1][lk + 2][lm] = wv2.z; Bs[buf ^ 1][lk + 3][lm] = wv2.w;  \
        }                                                                      \
        __syncthreads();                                                       \
        buf ^= 1;                                                              \
    }

#define GEMM_PROLOGUE                                                          \
    __shared__ float As[2][16][68];                                            \
    __shared__ float Bs[2][16][68];                                            \
    const int tid = threadIdx.x;                                               \
    const int tx = tid & 15, ty = tid >> 4;                                    \
    const int lm = tid >> 2;                                                   \
    const int lk = (tid & 3) * 4;

// ---------------------------------------------------------------------------
// Fused GRU input+hidden GEMM, split-K (round-2, proven)
// ---------------------------------------------------------------------------
__global__ __launch_bounds__(256) void gru_gemm_kernel(
    const float* __restrict__ emb, const float* __restrict__ W_ih,
    const float* __restrict__ W_hh, const float* __restrict__ hin)
{
    GEMM_PROLOGUE
    const int tile = blockIdx.x;
    const int kc = blockIdx.y;
    const bool is_gi = tile < 48;
    const int n0f = (tile % 48) * 64;
    const float* W = is_gi ? W_ih : W_hh;
    const float* arow = is_gi ? (emb + (size_t)g_tok[lm] * HH)
                              : (hin + (size_t)lm * HH);
    const float* wrow = W + (size_t)(n0f + lm) * KK;
    const int kbase = kc * (KK / GRU_KC);

    GEMM_CORE(arow, wrow, kbase, (KK / GRU_KC))

    float* outp = g_part[kc] + (is_gi ? 0 : 3 * HH);
    #pragma unroll
    for (int i = 0; i < 4; i++) {
        int m = ty * 4 + i;
        #pragma unroll
        for (int j = 0; j < 4; j++)
            outp[(size_t)m * 6 * HH + n0f + tx * 4 + j] = acc[i][j];
    }
}

__global__ void gru_gate_kernel(const float* __restrict__ hin,
                                float* __restrict__ hout,
                                const float* __restrict__ b_ih,
                                const float* __restrict__ b_hh)
{
    int idx = blockIdx.x * blockDim.x + threadIdx.x;
    if (idx >= BB * HH) return;
    int b = idx >> 10, j = idx & 1023;
    float ir = b_ih[j], iz = b_ih[HH + j], in_ = b_ih[2 * HH + j];
    float hr = b_hh[j], hz = b_hh[HH + j], hn = b_hh[2 * HH + j];
    #pragma unroll
    for (int c = 0; c < GRU_KC; c++) {
        const float* p = g_part[c] + (size_t)b * 6 * HH;
        ir += p[j];          iz += p[HH + j];     in_ += p[2 * HH + j];
        hr += p[3 * HH + j]; hz += p[4 * HH + j]; hn  += p[5 * HH + j];
    }
    float r = 1.f / (1.f + expf(-(ir + hr)));
    float z = 1.f / (1.f + expf(-(iz + hz)));
    float n = tanhf(in_ + r * hn);
    float h = (1.f - z) * n + z * hin[idx];
    hout[idx] = h;
    g_hb[idx] = __float2bfloat16(h);
}

// ---------------------------------------------------------------------------
// h0 projection with split-K (round-2, proven)
// ---------------------------------------------------------------------------
__global__ __launch_bounds__(256) void h0_gemm_kernel(
    const float* __restrict__ latent, const float* __restrict__ W_proj)
{
    GEMM_PROLOGUE
    const int n0 = blockIdx.x * 64;
    const int kc = blockIdx.y;
    const float* arow = latent + (size_t)lm * KK;
    const float* wrow = W_proj + (size_t)(n0 + lm) * KK;
    const int kbase = kc * (KK / H0_KC);

    GEMM_CORE(arow, wrow, kbase, (KK / H0_KC))

    #pragma unroll
    for (int i = 0; i < 4; i++) {
        int m = ty * 4 + i;
        #pragma unroll
        for (int j = 0; j < 4; j++)
            g_h0part[kc][(size_t)m * HH + n0 + tx * 4 + j] = acc[i][j];
    }
}

__global__ void h0_reduce_kernel(float* __restrict__ h,
                                 const float* __restrict__ b_proj)
{
    int idx = blockIdx.x * blockDim.x + threadIdx.x;
    if (idx >= BB * HH) return;
    int j = idx & 1023;
    float s = b_proj[j];
    #pragma unroll
    for (int c = 0; c < H0_KC; c++) s += g_h0part[c][idx];
    h[idx] = s;
    g_hb[idx] = __float2bfloat16(s);
}

// ---------------------------------------------------------------------------
// bf16 wmma screening (identical to round 4 — under test, not on token path)
// ---------------------------------------------------------------------------
__global__ __launch_bounds__(256) void logits_screen_kernel()
{
    const int w = threadIdx.x >> 5;
    const int mtile = w & 3;
    const int n0 = blockIdx.x * 128 + (w >> 2) * 64;

    wmma::fragment<wmma::accumulator, 16, 16, 16, float> c[4];
    #pragma unroll
    for (int i = 0; i < 4; i++) wmma::fill_fragment(c[i], 0.0f);

    const __nv_bfloat16* abase = g_hb + (size_t)mtile * 16 * HH;

    for (int k0 = 0; k0 < KK; k0 += 16) {
        wmma::fragment<wmma::matrix_a, 16, 16, 16, __nv_bfloat16,
                       wmma::row_major> a;
        wmma::load_matrix_sync(a, abase + k0, HH);
        #pragma unroll
        for (int nt = 0; nt < 4; nt++) {
            wmma::fragment<wmma::matrix_b, 16, 16, 16, __nv_bfloat16,
                           wmma::col_major> b;
            wmma::load_matrix_sync(b, g_Wb + (size_t)(n0 + nt * 16) * HH + k0,
                                   HH);
            wmma::mma_sync(c[nt], a, b, c[nt]);
        }
    }

    #pragma unroll
    for (int nt = 0; nt < 4; nt++)
        wmma::store_matrix_sync(&g_slog[mtile * 16][n0 + nt * 16], c[nt], VV,
                                wmma::mem_row_major);
}

// ---------------------------------------------------------------------------
// Exact fp32 logits + blockwise argmax (round-2, proven token path)
// ---------------------------------------------------------------------------
__global__ __launch_bounds__(256) void logits_argmax_kernel(
    const float* __restrict__ A, const float* __restrict__ W,
    const float* __restrict__ bias)
{
    GEMM_PROLOGUE
    __shared__ float rv[64][16];
    __shared__ int   ri[64][16];
    const int v0 = blockIdx.x * 64;
    const float* arow = A + (size_t)lm * KK;
    const float* wrow = W + (size_t)(v0 + lm) * KK;

    GEMM_CORE(arow, wrow, 0, KK)

    #pragma unroll
    for (int i = 0; i < 4; i++) {
        int m = ty * 4 + i;
        float best = -FLT_MAX; int bidx = VV;
        #pragma unroll
        for (int j = 0; j < 4; j++) {
            int v = v0 + tx * 4 + j;
            float val = acc[i][j] + bias[v];
            if (val > best) { best = val; bidx = v; }
        }
        rv[m][tx] = best; ri[m][tx] = bidx;
    }
    __syncthreads();

    if (tid < 64) {
        float best = rv[tid][0]; int bi = ri[tid][0];
        #pragma unroll
        for (int t = 1; t < 16; t++) {
            float v = rv[tid][t]; int idx = ri[tid][t];
            if (v > best || (v == best && idx < bi)) { best = v; bi = idx; }
        }
        g_pval[(size_t)tid * NBLK + blockIdx.x] = best;
        g_pidx[(size_t)tid * NBLK + blockIdx.x] = bi;
    }
}

__global__ __launch_bounds__(256) void finalize_kernel(int t, float* __restrict__ out)
{
    int b = blockIdx.x;
    __shared__ float sv[256];
    __shared__ int   si[256];
    float best = -FLT_MAX; int bi = VV;
    for (int i = threadIdx.x; i < NBLK; i += 256) {
        float v = g_pval[(size_t)b * NBLK + i];
        int idx  = g_pidx[(size_t)b * NBLK + i];
        if (v > best || (v == best && idx < bi)) { best = v; bi = idx; }
    }
    sv[threadIdx.x] = best; si[threadIdx.x] = bi;
    __syncthreads();
    for (int s = 128; s > 0; s >>= 1) {
        if (threadIdx.x < s) {
            float v = sv[threadIdx.x + s]; int idx = si[threadIdx.x + s];
            if (v > sv[threadIdx.x] ||
                (v == sv[threadIdx.x] && idx < si[threadIdx.x])) {
                sv[threadIdx.x] = v; si[threadIdx.x] = idx;
            }
        }
        __syncthreads();
    }
    if (threadIdx.x == 0) {
        g_tok[b] = si[0];
        out[b * TT + t] = (float)si[0];
    }
}

// ---------------------------------------------------------------------------
// PROBE: per row, is the exact-argmax token within MARGIN of the screened
// max? On failure, spin so dur_us encodes the diagnosis. Writes nothing to
// the output path.
// ---------------------------------------------------------------------------
__global__ __launch_bounds__(256) void probe_kernel(const float* __restrict__ b_out)
{
    const int b = blockIdx.x;
    const int tid = threadIdx.x;
    const int lane = tid & 31, w = tid >> 5;
    __shared__ float red[8];

    float m = -FLT_MAX;
    for (int v = tid; v < VV; v += 256)
        m = fmaxf(m, g_slog[b][v] + b_out[v]);
    #pragma unroll
    for (int s = 16; s > 0; s >>= 1)
        m = fmaxf(m, __shfl_xor_sync(0xffffffffu, m, s));
    if (lane == 0) red[w] = m;
    __syncthreads();

    if (tid == 0) {
        float sM = red[0];
        #pragma unroll
        for (int i = 1; i < 8; i++) sM = fmaxf(sM, red[i]);
        const int tok = g_tok[b];
        const float tv = g_slog[b][tok] + b_out[tok];
        const bool covered = (tv >= sM - MARGIN);
        if (!covered) {
            const long long spin =
                (fabsf(sM) <= 1e-5f) ? SPIN_ZERO : SPIN_BAD;
            long long start = clock64();
            int x = 0;
            while (clock64() - start < spin) x++;
            g_probe_sink = x;   // keep the loop observable; never read
        }
    }
}

__global__ void copy_h_kernel(float* __restrict__ out, int out_size)
{
    int i = blockIdx.x * blockDim.x + threadIdx.x;
    if (i < BB * HH && (BB * TT + i) < out_size)
        out[BB * TT + i] = g_h[0][i];
}

// ---------------------------------------------------------------------------
extern "C" void kernel_launch(void* const* d_in, const int* in_sizes, int n_in,
                              void* d_out, int out_size)
{
    const float* latent = (const float*)d_in[0];
    const float* W_proj = (const float*)d_in[1];
    const float* b_proj = (const float*)d_in[2];
    const float* emb    = (const float*)d_in[3];
    const float* W_ih   = (const float*)d_in[4];
    const float* b_ih   = (const float*)d_in[5];
    const float* W_hh   = (const float*)d_in[6];
    const float* b_hh   = (const float*)d_in[7];
    const float* W_out  = (const float*)d_in[8];
    const float* b_out  = (const float*)d_in[9];
    float* out = (float*)d_out;

    float* p_h = nullptr;
    __nv_bfloat16* p_Wb = nullptr;
    cudaGetSymbolAddress((void**)&p_h,  g_h);
    cudaGetSymbolAddress((void**)&p_Wb, g_Wb);

    init_tok_kernel<<<1, 64>>>();
    wconv_kernel<<<(int)(((size_t)VV * HH / 4 + 255) / 256), 256>>>(W_out, p_Wb);

    h0_gemm_kernel<<<dim3(HH / 64, H0_KC), 256>>>(latent, W_proj);
    h0_reduce_kernel<<<(BB * HH + 255) / 256, 256>>>(p_h, b_proj);

    for (int t = 0; t < TT; t++) {
        const float* hin  = p_h + (t & 1) * (BB * HH);
        float*       hout = p_h + ((t + 1) & 1) * (BB * HH);

        gru_gemm_kernel<<<dim3(96, GRU_KC), 256>>>(emb, W_ih, W_hh, hin);
        gru_gate_kernel<<<(BB * HH + 255) / 256, 256>>>(hin, hout, b_ih, b_hh);

        // Screening under test (not on token path)
        logits_screen_kernel<<<NSCR, 256>>>();

        // Exact token path (proven)
        logits_argmax_kernel<<<NBLK, 256>>>(hout, W_out, b_out);
        finalize_kernel<<<BB, 256>>>(t, out);

        // Diagnosis: dur_us encodes screen correctness
        probe_kernel<<<BB, 256>>>(b_out);
    }

    copy_h_kernel<<<(BB * HH + 255) / 256, 256>>>(out, out_size);
}